// round 12
// baseline (speedup 1.0000x reference)
#include <cuda_runtime.h>
#include <math.h>

#define H 1024
#define W 1024
#define NPIX (H * W)
#define NSL 16
#define HALF (8 * NPIX)

#define TXO 128
#define TYO 32
#define PADX 8
#define W2 144          // padded smem row; center pixels at lx = 8..135

__device__ float g_img0[NSL * NPIX];
__device__ float g_bufA[NSL * NPIX];
__device__ float g_skel[NSL * NPIX];
__device__ float g_acc[8];

__global__ void zero_acc_kernel() {
    if (threadIdx.x < 8) g_acc[threadIdx.x] = 0.0f;
}

__global__ void init_kernel(const float4* __restrict__ pred,
                            const int4* __restrict__ tgt) {
    float a4 = 0.f, a5 = 0.f, a6 = 0.f;
    const int n4 = HALF / 4;
    float4* img4 = (float4*)g_img0;
    const int stride = gridDim.x * blockDim.x;
    for (int i = blockIdx.x * blockDim.x + threadIdx.x; i < n4; i += stride) {
        float4 x = pred[i];
        int4 ti = tgt[i];
        float4 p, t;
        p.x = 1.0f / (1.0f + __expf(-x.x));
        p.y = 1.0f / (1.0f + __expf(-x.y));
        p.z = 1.0f / (1.0f + __expf(-x.z));
        p.w = 1.0f / (1.0f + __expf(-x.w));
        t.x = (float)ti.x; t.y = (float)ti.y; t.z = (float)ti.z; t.w = (float)ti.w;
        img4[i] = p;
        img4[n4 + i] = t;
        a4 += p.x * t.x + p.y * t.y + p.z * t.z + p.w * t.w;
        a5 += p.x + p.y + p.z + p.w;
        a6 += t.x + t.y + t.z + t.w;
    }
    #pragma unroll
    for (int o = 16; o; o >>= 1) {
        a4 += __shfl_down_sync(0xffffffffu, a4, o);
        a5 += __shfl_down_sync(0xffffffffu, a5, o);
        a6 += __shfl_down_sync(0xffffffffu, a6, o);
    }
    __shared__ float sr[3][8];
    int w = threadIdx.x >> 5, l = threadIdx.x & 31;
    if (l == 0) { sr[0][w] = a4; sr[1][w] = a5; sr[2][w] = a6; }
    __syncthreads();
    if (threadIdx.x == 0) {
        float s4 = 0.f, s5 = 0.f, s6 = 0.f;
        #pragma unroll
        for (int k = 0; k < 8; k++) { s4 += sr[0][k]; s5 += sr[1][k]; s6 += sr[2][k]; }
        atomicAdd(&g_acc[4], s4);
        atomicAdd(&g_acc[5], s5);
        atomicAdd(&g_acc[6], s6);
    }
}

// F fused steps; 512 threads; 2 rows/thread; 2-buffer pipeline, 1 barrier/step.
// ek (e_st center rows) is read from `cur` PRE-barrier, so the dilate phase
// touches only `nxt` and the next erode may overwrite old `cur` safely.
template<int F, bool FIRST, bool LAST>
__global__ __launch_bounds__(512, 3)
void fused_kernel(int src_sel, int dst_sel) {
    constexpr int R  = F + 1;
    constexpr int H2 = TYO + 2 * R;
    constexpr int BUF = H2 * W2;

    extern __shared__ float smem[];
    float* sX = smem;
    float* sY = smem + BUF;
    __shared__ float sred[32];

    const float* in = (src_sel == 0) ? g_img0 : g_bufA;
    float* eout = g_bufA;

    const int bx = blockIdx.x * TXO;
    const int by = blockIdx.y * TYO;
    const int z  = blockIdx.z;
    const float* img = in + z * NPIX;
    const int tx = threadIdx.x;        // 0..31
    const int ty = threadIdx.y;        // 0..15
    const int tid = ty * 32 + tx;
    const bool border = (blockIdx.x == 0) | (blockIdx.x == gridDim.x - 1) |
                        (blockIdx.y == 0) | (blockIdx.y == gridDim.y - 1);

    // ---- load tile with halo ----
    if (!border) {
        for (int i = tid; i < 36 * H2; i += 512) {
            int vy = i / 36, vx = i - vy * 36;
            *(float4*)&sX[vy * W2 + 4 * vx] =
                *(const float4*)&img[(by - R + vy) * W + (bx - PADX + 4 * vx)];
        }
    } else {
        for (int i = tid; i < 36 * H2; i += 512) {
            int vy = i / 36, vx = i - vy * 36;
            int gx0 = bx - PADX + 4 * vx;
            int gy  = by - R + vy;
            float4 v = make_float4(INFINITY, INFINITY, INFINITY, INFINITY);
            if ((unsigned)gx0 < W && (unsigned)gy < H)
                v = *(const float4*)&img[gy * W + gx0];
            *(float4*)&sX[vy * W2 + 4 * vx] = v;
        }
    }

    const int py0 = 2 * ty;
    const int gi0 = z * NPIX + (by + py0) * W + (bx + 4 * tx);
    const int gi1 = gi0 + W;
    const int oc = (R + py0) * W2 + PADX + 4 * tx;   // center offset (row py0)
    float4 sk0, sk1;
    if (FIRST) {
        sk0 = make_float4(0.f, 0.f, 0.f, 0.f);
        sk1 = sk0;
    } else {
        sk0 = *(const float4*)&g_skel[gi0];
        sk1 = *(const float4*)&g_skel[gi1];
    }
    __syncthreads();

    float* cur = sX;
    float* nxt = sY;

    #pragma unroll
    for (int st = 0; st < F; st++) {
        // ---- erode cur -> nxt; rows [1+st, H2-1-st) in pairs; vecs 0..35 ----
        // Edge vecs (0, 35) substitute +inf for the outside-tile scalar; this
        // corrupts only lx 0 / 143, which no later stage consumes.
        const int npairs = (H2 - 2 - 2 * st) >> 1;
        const int ntask = npairs * 36;
        for (int i = tid; i < ntask; i += 512) {
            int pj = i / 36;
            int vx = i - pj * 36;
            int y0 = 1 + st + 2 * pj;
            int o1 = y0 * W2 + 4 * vx;
            int o2 = o1 + W2;
            float4 c0 = *(float4*)&cur[o1 - W2];
            float4 c1 = *(float4*)&cur[o1];
            float4 c2 = *(float4*)&cur[o2];
            float4 c3 = *(float4*)&cur[o2 + W2];
            float l1 = (vx > 0)  ? cur[o1 - 1] : INFINITY;
            float r1 = (vx < 35) ? cur[o1 + 4] : INFINITY;
            float l2 = (vx > 0)  ? cur[o2 - 1] : INFINITY;
            float r2 = (vx < 35) ? cur[o2 + 4] : INFINITY;
            float4 e1, e2;
            e1.x = fminf(fminf(c1.x, fminf(c0.x, c2.x)), fminf(l1,   c1.y));
            e1.y = fminf(fminf(c1.y, fminf(c0.y, c2.y)), fminf(c1.x, c1.z));
            e1.z = fminf(fminf(c1.z, fminf(c0.z, c2.z)), fminf(c1.y, c1.w));
            e1.w = fminf(fminf(c1.w, fminf(c0.w, c2.w)), fminf(c1.z, r1));
            e2.x = fminf(fminf(c2.x, fminf(c1.x, c3.x)), fminf(l2,   c2.y));
            e2.y = fminf(fminf(c2.y, fminf(c1.y, c3.y)), fminf(c2.x, c2.z));
            e2.z = fminf(fminf(c2.z, fminf(c1.z, c3.z)), fminf(c2.y, c2.w));
            e2.w = fminf(fminf(c2.w, fminf(c1.w, c3.w)), fminf(c2.z, r2));
            if (border) {
                int gx0 = bx - PADX + 4 * vx;
                int gy  = by - R + y0;
                bool okx = (unsigned)gx0 < W;
                if (!(okx && (unsigned)gy < H))
                    e1 = make_float4(INFINITY, INFINITY, INFINITY, INFINITY);
                if (!(okx && (unsigned)(gy + 1) < H))
                    e2 = make_float4(INFINITY, INFINITY, INFINITY, INFINITY);
            }
            *(float4*)&nxt[o1] = e1;
            *(float4*)&nxt[o2] = e2;
        }

        // ---- capture e_st at own center rows (cur stable until barrier) ----
        float4 ek0 = *(float4*)&cur[oc];
        float4 ek1 = *(float4*)&cur[oc + W2];
        __syncthreads();

        // ---- dilate3x3(e_{st+1}) from nxt only + delta + skel ----
        {
            float4 ra = *(float4*)&nxt[oc - W2];
            float4 rb = *(float4*)&nxt[oc];
            float4 rc = *(float4*)&nxt[oc + W2];
            float4 rd = *(float4*)&nxt[oc + 2 * W2];
            float la = nxt[oc - W2 - 1],     rra = nxt[oc - W2 + 4];
            float lb = nxt[oc - 1],          rrb = nxt[oc + 4];
            float lc = nxt[oc + W2 - 1],     rrc = nxt[oc + W2 + 4];
            float ld = nxt[oc + 2 * W2 - 1], rrd = nxt[oc + 2 * W2 + 4];
            if (border) {
                const int gy0 = by + py0;
                const int gx0 = bx + 4 * tx;
                if (gy0 == 0) {
                    ra = make_float4(-INFINITY, -INFINITY, -INFINITY, -INFINITY);
                    la = -INFINITY; rra = -INFINITY;
                }
                if (gy0 + 1 == H - 1) {
                    rd = make_float4(-INFINITY, -INFINITY, -INFINITY, -INFINITY);
                    ld = -INFINITY; rrd = -INFINITY;
                }
                if (gx0 == 0)     { la = -INFINITY; lb = -INFINITY; lc = -INFINITY; ld = -INFINITY; }
                if (gx0 == W - 4) { rra = -INFINITY; rrb = -INFINITY; rrc = -INFINITY; rrd = -INFINITY; }
            }
            float4 ha, hb, hc, hd;
            ha.x = fmaxf(la,   fmaxf(ra.x, ra.y));
            ha.y = fmaxf(ra.x, fmaxf(ra.y, ra.z));
            ha.z = fmaxf(ra.y, fmaxf(ra.z, ra.w));
            ha.w = fmaxf(ra.z, fmaxf(ra.w, rra));
            hb.x = fmaxf(lb,   fmaxf(rb.x, rb.y));
            hb.y = fmaxf(rb.x, fmaxf(rb.y, rb.z));
            hb.z = fmaxf(rb.y, fmaxf(rb.z, rb.w));
            hb.w = fmaxf(rb.z, fmaxf(rb.w, rrb));
            hc.x = fmaxf(lc,   fmaxf(rc.x, rc.y));
            hc.y = fmaxf(rc.x, fmaxf(rc.y, rc.z));
            hc.z = fmaxf(rc.y, fmaxf(rc.z, rc.w));
            hc.w = fmaxf(rc.z, fmaxf(rc.w, rrc));
            hd.x = fmaxf(ld,   fmaxf(rd.x, rd.y));
            hd.y = fmaxf(rd.x, fmaxf(rd.y, rd.z));
            hd.z = fmaxf(rd.y, fmaxf(rd.z, rd.w));
            hd.w = fmaxf(rd.z, fmaxf(rd.w, rrd));

            float4 d0, d1;
            d0.x = fmaxf(ha.x, fmaxf(hb.x, hc.x));
            d0.y = fmaxf(ha.y, fmaxf(hb.y, hc.y));
            d0.z = fmaxf(ha.z, fmaxf(hb.z, hc.z));
            d0.w = fmaxf(ha.w, fmaxf(hb.w, hc.w));
            d1.x = fmaxf(hb.x, fmaxf(hc.x, hd.x));
            d1.y = fmaxf(hb.y, fmaxf(hc.y, hd.y));
            d1.z = fmaxf(hb.z, fmaxf(hc.z, hd.z));
            d1.w = fmaxf(hb.w, fmaxf(hc.w, hd.w));

            float4 de0, de1;
            de0.x = fmaxf(ek0.x - d0.x, 0.f);
            de0.y = fmaxf(ek0.y - d0.y, 0.f);
            de0.z = fmaxf(ek0.z - d0.z, 0.f);
            de0.w = fmaxf(ek0.w - d0.w, 0.f);
            de1.x = fmaxf(ek1.x - d1.x, 0.f);
            de1.y = fmaxf(ek1.y - d1.y, 0.f);
            de1.z = fmaxf(ek1.z - d1.z, 0.f);
            de1.w = fmaxf(ek1.w - d1.w, 0.f);
            if (FIRST && st == 0) {
                sk0 = de0; sk1 = de1;
            } else {
                sk0.x += fmaxf(de0.x - sk0.x * de0.x, 0.f);
                sk0.y += fmaxf(de0.y - sk0.y * de0.y, 0.f);
                sk0.z += fmaxf(de0.z - sk0.z * de0.z, 0.f);
                sk0.w += fmaxf(de0.w - sk0.w * de0.w, 0.f);
                sk1.x += fmaxf(de1.x - sk1.x * de1.x, 0.f);
                sk1.y += fmaxf(de1.y - sk1.y * de1.y, 0.f);
                sk1.z += fmaxf(de1.z - sk1.z * de1.z, 0.f);
                sk1.w += fmaxf(de1.w - sk1.w * de1.w, 0.f);
            }
            if (st == F - 1 && !LAST) {
                *(float4*)&eout[gi0] = rb;
                *(float4*)&eout[gi1] = rc;
                *(float4*)&g_skel[gi0] = sk0;
                *(float4*)&g_skel[gi1] = sk1;
            }
        }
        // swap: next erode writes old cur (no live readers), reads nxt.
        float* t0 = cur; cur = nxt; nxt = t0;
    }

    if (LAST) {
        float4 cp0 = (z < 8) ? *(const float4*)&g_img0[gi0 + HALF]
                             : *(const float4*)&g_img0[gi0 - HALF];
        float4 cp1 = (z < 8) ? *(const float4*)&g_img0[gi1 + HALF]
                             : *(const float4*)&g_img0[gi1 - HALF];
        float sprod = sk0.x * cp0.x + sk0.y * cp0.y + sk0.z * cp0.z + sk0.w * cp0.w
                    + sk1.x * cp1.x + sk1.y * cp1.y + sk1.z * cp1.z + sk1.w * cp1.w;
        float ssum  = sk0.x + sk0.y + sk0.z + sk0.w
                    + sk1.x + sk1.y + sk1.z + sk1.w;
        #pragma unroll
        for (int o = 16; o; o >>= 1) {
            sprod += __shfl_down_sync(0xffffffffu, sprod, o);
            ssum  += __shfl_down_sync(0xffffffffu, ssum,  o);
        }
        int w = tid >> 5, l = tid & 31;
        if (l == 0) { sred[w] = sprod; sred[16 + w] = ssum; }
        __syncthreads();
        if (tid < 32) {
            float v = sred[tid];
            v += __shfl_down_sync(0xffffffffu, v, 8, 16);
            v += __shfl_down_sync(0xffffffffu, v, 4, 16);
            v += __shfl_down_sync(0xffffffffu, v, 2, 16);
            v += __shfl_down_sync(0xffffffffu, v, 1, 16);
            if (tid == 0) {
                if (z < 8) atomicAdd(&g_acc[0], v); else atomicAdd(&g_acc[2], v);
            }
            if (tid == 16) {
                if (z < 8) atomicAdd(&g_acc[1], v); else atomicAdd(&g_acc[3], v);
            }
        }
    }
}

__global__ void finalize_kernel(float* out) {
    const float SMOOTH = 1.0f;
    float tprec = (g_acc[0] + SMOOTH) / (g_acc[1] + SMOOTH);
    float tsens = (g_acc[2] + SMOOTH) / (g_acc[3] + SMOOTH);
    float cl_dice = 2.0f * tprec * tsens / (tprec + tsens + 1e-7f);
    float dice = (2.0f * g_acc[4] + SMOOTH) / (g_acc[5] + g_acc[6] + SMOOTH);
    float combined = 0.5f * dice + 0.5f * cl_dice;
    out[0] = 1.0f - combined;
}

extern "C" void kernel_launch(void* const* d_in, const int* in_sizes, int n_in,
                              void* d_out, int out_size) {
    const float4* pred = (const float4*)d_in[0];
    const int4* target = (const int4*)d_in[1];

    constexpr int SMEM_F6 = 2 * (TYO + 14) * W2 * 4;   // 2*46*144*4 = 52992 B
    constexpr int SMEM_F5 = 2 * (TYO + 12) * W2 * 4;   // 2*44*144*4 = 50688 B
    static bool attr_done = false;
    if (!attr_done) {
        cudaFuncSetAttribute(fused_kernel<6, true,  false>,
                             cudaFuncAttributeMaxDynamicSharedMemorySize, SMEM_F6);
        cudaFuncSetAttribute(fused_kernel<5, false, true>,
                             cudaFuncAttributeMaxDynamicSharedMemorySize, SMEM_F5);
        attr_done = true;
    }

    zero_acc_kernel<<<1, 32>>>();
    init_kernel<<<2048, 256>>>(pred, target);

    dim3 blk(32, 16);
    dim3 grd(W / TXO, H / TYO, NSL);
    fused_kernel<6, true,  false><<<grd, blk, SMEM_F6>>>(0, 1);  // steps 0-5
    fused_kernel<5, false, true ><<<grd, blk, SMEM_F5>>>(1, 1);  // steps 6-10

    finalize_kernel<<<1, 1>>>((float*)d_out);
}

// round 15
// speedup vs baseline: 1.0465x; 1.0465x over previous
#include <cuda_runtime.h>
#include <math.h>

#define H 1024
#define W 1024
#define NPIX (H * W)
#define NSL 16
#define HALF (8 * NPIX)

#define TXO 128
#define TYO 32
#define PADX 8
#define W2 144          // padded smem row; center pixels at lx = 8..135

__device__ float g_img0[NSL * NPIX];
__device__ float g_bufA[NSL * NPIX];
__device__ float g_bufB[NSL * NPIX];
__device__ float g_skel[NSL * NPIX];
__device__ float g_acc[8];

__global__ void zero_acc_kernel() {
    if (threadIdx.x < 8) g_acc[threadIdx.x] = 0.0f;
}

__global__ void init_kernel(const float4* __restrict__ pred,
                            const int4* __restrict__ tgt) {
    float a4 = 0.f, a5 = 0.f, a6 = 0.f;
    const int n4 = HALF / 4;
    float4* img4 = (float4*)g_img0;
    const int stride = gridDim.x * blockDim.x;
    for (int i = blockIdx.x * blockDim.x + threadIdx.x; i < n4; i += stride) {
        float4 x = pred[i];
        int4 ti = tgt[i];
        float4 p, t;
        p.x = 1.0f / (1.0f + __expf(-x.x));
        p.y = 1.0f / (1.0f + __expf(-x.y));
        p.z = 1.0f / (1.0f + __expf(-x.z));
        p.w = 1.0f / (1.0f + __expf(-x.w));
        t.x = (float)ti.x; t.y = (float)ti.y; t.z = (float)ti.z; t.w = (float)ti.w;
        img4[i] = p;
        img4[n4 + i] = t;
        a4 += p.x * t.x + p.y * t.y + p.z * t.z + p.w * t.w;
        a5 += p.x + p.y + p.z + p.w;
        a6 += t.x + t.y + t.z + t.w;
    }
    #pragma unroll
    for (int o = 16; o; o >>= 1) {
        a4 += __shfl_down_sync(0xffffffffu, a4, o);
        a5 += __shfl_down_sync(0xffffffffu, a5, o);
        a6 += __shfl_down_sync(0xffffffffu, a6, o);
    }
    __shared__ float sr[3][8];
    int w = threadIdx.x >> 5, l = threadIdx.x & 31;
    if (l == 0) { sr[0][w] = a4; sr[1][w] = a5; sr[2][w] = a6; }
    __syncthreads();
    if (threadIdx.x == 0) {
        float s4 = 0.f, s5 = 0.f, s6 = 0.f;
        #pragma unroll
        for (int k = 0; k < 8; k++) { s4 += sr[0][k]; s5 += sr[1][k]; s6 += sr[2][k]; }
        atomicAdd(&g_acc[4], s4);
        atomicAdd(&g_acc[5], s5);
        atomicAdd(&g_acc[6], s6);
    }
}

__device__ __forceinline__ float4 erode5(float4 u, float4 c, float4 d, float l, float r) {
    float4 e;
    e.x = fminf(fminf(c.x, fminf(u.x, d.x)), fminf(l,   c.y));
    e.y = fminf(fminf(c.y, fminf(u.y, d.y)), fminf(c.x, c.z));
    e.z = fminf(fminf(c.z, fminf(u.z, d.z)), fminf(c.y, c.w));
    e.w = fminf(fminf(c.w, fminf(u.w, d.w)), fminf(c.z, r));
    return e;
}

__device__ __forceinline__ float4 hmax3(float l, float4 v, float r) {
    float4 h;
    h.x = fmaxf(l,   fmaxf(v.x, v.y));
    h.y = fmaxf(v.x, fmaxf(v.y, v.z));
    h.z = fmaxf(v.y, fmaxf(v.z, v.w));
    h.w = fmaxf(v.z, fmaxf(v.w, r));
    return h;
}

// F fused steps; dilate(step k) + erode(step k+1) share ONE read pass of
// e_{k+1}; center erode is register-only (reuses dilate's loads); ek for the
// next delta is carried in registers (rb,rc). 2 static smem buffers.
template<int F, bool FIRST, bool LAST>
__global__ __launch_bounds__(512, 3)
void fused_kernel(int src_sel, int dst_sel) {
    constexpr int R  = F + 1;
    constexpr int H2 = TYO + 2 * R;
    constexpr int BUF = H2 * W2;

    __shared__ float sX[BUF];
    __shared__ float sY[BUF];
    __shared__ float sred[32];

    const float* in = (src_sel == 0) ? g_img0 : ((src_sel == 1) ? g_bufA : g_bufB);
    float* eout = (dst_sel == 1) ? g_bufA : g_bufB;

    const int bx = blockIdx.x * TXO;
    const int by = blockIdx.y * TYO;
    const int z  = blockIdx.z;
    const float* img = in + z * NPIX;
    const int tx = threadIdx.x;        // 0..31
    const int ty = threadIdx.y;        // 0..15
    const int tid = ty * 32 + tx;
    const bool border = (blockIdx.x == 0) | (blockIdx.x == gridDim.x - 1) |
                        (blockIdx.y == 0) | (blockIdx.y == gridDim.y - 1);

    // ---- load e_0 tile with halo into sX ----
    if (!border) {
        for (int i = tid; i < 36 * H2; i += 512) {
            int vy = i / 36, vx = i - vy * 36;
            *(float4*)&sX[vy * W2 + 4 * vx] =
                *(const float4*)&img[(by - R + vy) * W + (bx - PADX + 4 * vx)];
        }
    } else {
        for (int i = tid; i < 36 * H2; i += 512) {
            int vy = i / 36, vx = i - vy * 36;
            int gx0 = bx - PADX + 4 * vx;
            int gy  = by - R + vy;
            float4 v = make_float4(INFINITY, INFINITY, INFINITY, INFINITY);
            if ((unsigned)gx0 < W && (unsigned)gy < H)
                v = *(const float4*)&img[gy * W + gx0];
            *(float4*)&sX[vy * W2 + 4 * vx] = v;
        }
    }

    const int py0 = 2 * ty;
    const int gi0 = z * NPIX + (by + py0) * W + (bx + 4 * tx);
    const int gi1 = gi0 + W;
    const int oc = (R + py0) * W2 + PADX + 4 * tx;
    const int gx0c = bx + 4 * tx;
    const int gy0c = by + py0;

    float4 sk0, sk1;
    if (FIRST) {
        sk0 = make_float4(0.f, 0.f, 0.f, 0.f);
        sk1 = sk0;
    } else {
        sk0 = *(const float4*)&g_skel[gi0];
        sk1 = *(const float4*)&g_skel[gi1];
    }
    __syncthreads();

    // ---- initial erode e_0(sX) -> e_1(sY): rows [1,H2-1), vecs 0..35 ----
    {
        const int npairs = (H2 - 2) >> 1;
        const int ntask = npairs * 36;
        for (int i = tid; i < ntask; i += 512) {
            int pj = i / 36;
            int vx = i - pj * 36;
            int y0 = 1 + 2 * pj;
            int o1 = y0 * W2 + 4 * vx;
            int o2 = o1 + W2;
            float4 c0 = *(float4*)&sX[o1 - W2];
            float4 c1 = *(float4*)&sX[o1];
            float4 c2 = *(float4*)&sX[o2];
            float4 c3 = *(float4*)&sX[o2 + W2];
            float l1 = (vx > 0)  ? sX[o1 - 1] : INFINITY;
            float r1 = (vx < 35) ? sX[o1 + 4] : INFINITY;
            float l2 = (vx > 0)  ? sX[o2 - 1] : INFINITY;
            float r2 = (vx < 35) ? sX[o2 + 4] : INFINITY;
            float4 e1 = erode5(c0, c1, c2, l1, r1);
            float4 e2 = erode5(c1, c2, c3, l2, r2);
            if (border) {
                int gx0 = bx - PADX + 4 * vx;
                int gy  = by - R + y0;
                bool okx = (unsigned)gx0 < W;
                if (!(okx && (unsigned)gy < H))
                    e1 = make_float4(INFINITY, INFINITY, INFINITY, INFINITY);
                if (!(okx && (unsigned)(gy + 1) < H))
                    e2 = make_float4(INFINITY, INFINITY, INFINITY, INFINITY);
            }
            *(float4*)&sY[o1] = e1;
            *(float4*)&sY[o2] = e2;
        }
    }
    // capture ek = e_0 centers (sX stable until barrier)
    float4 ek0 = *(float4*)&sX[oc];
    float4 ek1 = *(float4*)&sX[oc + W2];
    __syncthreads();

    float* cur = sY;   // e_{st+1}
    float* oth = sX;   // erode target (e_{st+2})

    #pragma unroll
    for (int st = 0; st < F; st++) {
        // ---- halo erode tasks (only for st < F-1) ----
        if (st < F - 1) {
            const int nh = F - 1 - st;                 // rows per side
            const int ntaskA = 2 * nh * 34;            // halo rows, vecs 1..34
            const int ntaskB = 64;                     // center rows, vecs {1,34}
            for (int i = tid; i < ntaskA + ntaskB; i += 512) {
                int y, vx;
                if (i < ntaskA) {
                    int j = i / 34;
                    vx = i - j * 34 + 1;
                    y = (j < nh) ? (st + 2 + j) : (R + TYO + (j - nh));
                } else {
                    int k = i - ntaskA;
                    vx = (k < 32) ? 1 : 34;
                    y = R + (k & 31);
                }
                int o = y * W2 + 4 * vx;
                float4 c = *(float4*)&cur[o];
                float4 u = *(float4*)&cur[o - W2];
                float4 d = *(float4*)&cur[o + W2];
                float l = cur[o - 1], r = cur[o + 4];
                float4 e = erode5(u, c, d, l, r);
                if (border) {
                    int gx0 = bx - PADX + 4 * vx;
                    int gy  = by - R + y;
                    if (!((unsigned)gx0 < W && (unsigned)gy < H))
                        e = make_float4(INFINITY, INFINITY, INFINITY, INFINITY);
                }
                *(float4*)&oth[o] = e;
            }
        }

        // ---- center: one read pass of cur serves dilate AND erode ----
        {
            float4 ra = *(float4*)&cur[oc - W2];
            float4 rb = *(float4*)&cur[oc];
            float4 rc = *(float4*)&cur[oc + W2];
            float4 rd = *(float4*)&cur[oc + 2 * W2];
            float la = cur[oc - W2 - 1],     rra = cur[oc - W2 + 4];
            float lb = cur[oc - 1],          rrb = cur[oc + 4];
            float lc = cur[oc + W2 - 1],     rrc = cur[oc + W2 + 4];
            float ld = cur[oc + 2 * W2 - 1], rrd = cur[oc + 2 * W2 + 4];

            // center erode (raw values; +inf fix at image x-edges)
            if (st < F - 1) {
                float elb = lb, erb = rrb, elc = lc, erc = rrc;
                if (border) {
                    if (gx0c == 0)     { elb = INFINITY; elc = INFINITY; }
                    if (gx0c == W - 4) { erb = INFINITY; erc = INFINITY; }
                }
                float4 e0 = erode5(ra, rb, rc, elb, erb);
                float4 e1 = erode5(rb, rc, rd, elc, erc);
                *(float4*)&oth[oc] = e0;
                *(float4*)&oth[oc + W2] = e1;
            }

            // dilate masks (applied AFTER erode consumed raw values)
            if (border) {
                if (gy0c == 0) {
                    ra = make_float4(-INFINITY, -INFINITY, -INFINITY, -INFINITY);
                    la = -INFINITY; rra = -INFINITY;
                }
                if (gy0c + 1 == H - 1) {
                    rd = make_float4(-INFINITY, -INFINITY, -INFINITY, -INFINITY);
                    ld = -INFINITY; rrd = -INFINITY;
                }
                if (gx0c == 0)     { la = -INFINITY; lb = -INFINITY; lc = -INFINITY; ld = -INFINITY; }
                if (gx0c == W - 4) { rra = -INFINITY; rrb = -INFINITY; rrc = -INFINITY; rrd = -INFINITY; }
            }
            float4 ha = hmax3(la, ra, rra);
            float4 hb = hmax3(lb, rb, rrb);
            float4 hc = hmax3(lc, rc, rrc);
            float4 hd = hmax3(ld, rd, rrd);

            float4 d0, d1;
            d0.x = fmaxf(ha.x, fmaxf(hb.x, hc.x));
            d0.y = fmaxf(ha.y, fmaxf(hb.y, hc.y));
            d0.z = fmaxf(ha.z, fmaxf(hb.z, hc.z));
            d0.w = fmaxf(ha.w, fmaxf(hb.w, hc.w));
            d1.x = fmaxf(hb.x, fmaxf(hc.x, hd.x));
            d1.y = fmaxf(hb.y, fmaxf(hc.y, hd.y));
            d1.z = fmaxf(hb.z, fmaxf(hc.z, hd.z));
            d1.w = fmaxf(hb.w, fmaxf(hc.w, hd.w));

            float4 de0, de1;
            de0.x = fmaxf(ek0.x - d0.x, 0.f);
            de0.y = fmaxf(ek0.y - d0.y, 0.f);
            de0.z = fmaxf(ek0.z - d0.z, 0.f);
            de0.w = fmaxf(ek0.w - d0.w, 0.f);
            de1.x = fmaxf(ek1.x - d1.x, 0.f);
            de1.y = fmaxf(ek1.y - d1.y, 0.f);
            de1.z = fmaxf(ek1.z - d1.z, 0.f);
            de1.w = fmaxf(ek1.w - d1.w, 0.f);
            if (FIRST && st == 0) {
                sk0 = de0; sk1 = de1;
            } else {
                sk0.x += fmaxf(de0.x - sk0.x * de0.x, 0.f);
                sk0.y += fmaxf(de0.y - sk0.y * de0.y, 0.f);
                sk0.z += fmaxf(de0.z - sk0.z * de0.z, 0.f);
                sk0.w += fmaxf(de0.w - sk0.w * de0.w, 0.f);
                sk1.x += fmaxf(de1.x - sk1.x * de1.x, 0.f);
                sk1.y += fmaxf(de1.y - sk1.y * de1.y, 0.f);
                sk1.z += fmaxf(de1.z - sk1.z * de1.z, 0.f);
                sk1.w += fmaxf(de1.w - sk1.w * de1.w, 0.f);
            }

            // carry e_{st+1} centers as next step's ek (zero loads)
            ek0 = rb;
            ek1 = rc;

            if (st == F - 1 && !LAST) {
                *(float4*)&eout[gi0] = rb;
                *(float4*)&eout[gi1] = rc;
                *(float4*)&g_skel[gi0] = sk0;
                *(float4*)&g_skel[gi1] = sk1;
            }
        }
        __syncthreads();
        float* t0 = cur; cur = oth; oth = t0;
    }

    if (LAST) {
        float4 cp0 = (z < 8) ? *(const float4*)&g_img0[gi0 + HALF]
                             : *(const float4*)&g_img0[gi0 - HALF];
        float4 cp1 = (z < 8) ? *(const float4*)&g_img0[gi1 + HALF]
                             : *(const float4*)&g_img0[gi1 - HALF];
        float sprod = sk0.x * cp0.x + sk0.y * cp0.y + sk0.z * cp0.z + sk0.w * cp0.w
                    + sk1.x * cp1.x + sk1.y * cp1.y + sk1.z * cp1.z + sk1.w * cp1.w;
        float ssum  = sk0.x + sk0.y + sk0.z + sk0.w
                    + sk1.x + sk1.y + sk1.z + sk1.w;
        #pragma unroll
        for (int o = 16; o; o >>= 1) {
            sprod += __shfl_down_sync(0xffffffffu, sprod, o);
            ssum  += __shfl_down_sync(0xffffffffu, ssum,  o);
        }
        int w = tid >> 5, l = tid & 31;
        if (l == 0) { sred[w] = sprod; sred[16 + w] = ssum; }
        __syncthreads();
        if (tid < 32) {
            float v = sred[tid];
            v += __shfl_down_sync(0xffffffffu, v, 8, 16);
            v += __shfl_down_sync(0xffffffffu, v, 4, 16);
            v += __shfl_down_sync(0xffffffffu, v, 2, 16);
            v += __shfl_down_sync(0xffffffffu, v, 1, 16);
            if (tid == 0) {
                if (z < 8) atomicAdd(&g_acc[0], v); else atomicAdd(&g_acc[2], v);
            }
            if (tid == 16) {
                if (z < 8) atomicAdd(&g_acc[1], v); else atomicAdd(&g_acc[3], v);
            }
        }
    }
}

__global__ void finalize_kernel(float* out) {
    const float SMOOTH = 1.0f;
    float tprec = (g_acc[0] + SMOOTH) / (g_acc[1] + SMOOTH);
    float tsens = (g_acc[2] + SMOOTH) / (g_acc[3] + SMOOTH);
    float cl_dice = 2.0f * tprec * tsens / (tprec + tsens + 1e-7f);
    float dice = (2.0f * g_acc[4] + SMOOTH) / (g_acc[5] + g_acc[6] + SMOOTH);
    float combined = 0.5f * dice + 0.5f * cl_dice;
    out[0] = 1.0f - combined;
}

extern "C" void kernel_launch(void* const* d_in, const int* in_sizes, int n_in,
                              void* d_out, int out_size) {
    const float4* pred = (const float4*)d_in[0];
    const int4* target = (const int4*)d_in[1];

    zero_acc_kernel<<<1, 32>>>();
    init_kernel<<<2048, 256>>>(pred, target);

    dim3 blk(32, 16);
    dim3 grd(W / TXO, H / TYO, NSL);
    fused_kernel<4, true,  false><<<grd, blk>>>(0, 1);  // steps 0-3, img0 -> A
    fused_kernel<4, false, false><<<grd, blk>>>(1, 2);  // steps 4-7, A -> B
    fused_kernel<3, false, true ><<<grd, blk>>>(2, 2);  // steps 8-10, B -> (sums)

    finalize_kernel<<<1, 1>>>((float*)d_out);
}

// round 16
// speedup vs baseline: 1.2365x; 1.1815x over previous
#include <cuda_runtime.h>
#include <math.h>

#define H 1024
#define W 1024
#define NPIX (H * W)
#define NSL 16
#define HALF (8 * NPIX)

#define TXO 128
#define TYO 64
#define PADX 8
#define W2 144          // padded smem row; center pixels at lx = 8..135

__device__ float g_img0[NSL * NPIX];
__device__ float g_bufA[NSL * NPIX];
__device__ float g_bufB[NSL * NPIX];
__device__ float g_skel[NSL * NPIX];
__device__ float g_acc[8];

__global__ void zero_acc_kernel() {
    if (threadIdx.x < 8) g_acc[threadIdx.x] = 0.0f;
}

__global__ void init_kernel(const float4* __restrict__ pred,
                            const int4* __restrict__ tgt) {
    float a4 = 0.f, a5 = 0.f, a6 = 0.f;
    const int n4 = HALF / 4;
    float4* img4 = (float4*)g_img0;
    const int stride = gridDim.x * blockDim.x;
    for (int i = blockIdx.x * blockDim.x + threadIdx.x; i < n4; i += stride) {
        float4 x = pred[i];
        int4 ti = tgt[i];
        float4 p, t;
        p.x = 1.0f / (1.0f + __expf(-x.x));
        p.y = 1.0f / (1.0f + __expf(-x.y));
        p.z = 1.0f / (1.0f + __expf(-x.z));
        p.w = 1.0f / (1.0f + __expf(-x.w));
        t.x = (float)ti.x; t.y = (float)ti.y; t.z = (float)ti.z; t.w = (float)ti.w;
        img4[i] = p;
        img4[n4 + i] = t;
        a4 += p.x * t.x + p.y * t.y + p.z * t.z + p.w * t.w;
        a5 += p.x + p.y + p.z + p.w;
        a6 += t.x + t.y + t.z + t.w;
    }
    #pragma unroll
    for (int o = 16; o; o >>= 1) {
        a4 += __shfl_down_sync(0xffffffffu, a4, o);
        a5 += __shfl_down_sync(0xffffffffu, a5, o);
        a6 += __shfl_down_sync(0xffffffffu, a6, o);
    }
    __shared__ float sr[3][8];
    int w = threadIdx.x >> 5, l = threadIdx.x & 31;
    if (l == 0) { sr[0][w] = a4; sr[1][w] = a5; sr[2][w] = a6; }
    __syncthreads();
    if (threadIdx.x == 0) {
        float s4 = 0.f, s5 = 0.f, s6 = 0.f;
        #pragma unroll
        for (int k = 0; k < 8; k++) { s4 += sr[0][k]; s5 += sr[1][k]; s6 += sr[2][k]; }
        atomicAdd(&g_acc[4], s4);
        atomicAdd(&g_acc[5], s5);
        atomicAdd(&g_acc[6], s6);
    }
}

__device__ __forceinline__ float4 erode5(float4 u, float4 c, float4 d, float l, float r) {
    float4 e;
    e.x = fminf(fminf(c.x, fminf(u.x, d.x)), fminf(l,   c.y));
    e.y = fminf(fminf(c.y, fminf(u.y, d.y)), fminf(c.x, c.z));
    e.z = fminf(fminf(c.z, fminf(u.z, d.z)), fminf(c.y, c.w));
    e.w = fminf(fminf(c.w, fminf(u.w, d.w)), fminf(c.z, r));
    return e;
}

__device__ __forceinline__ float4 hmax3(float l, float4 v, float r) {
    float4 h;
    h.x = fmaxf(l,   fmaxf(v.x, v.y));
    h.y = fmaxf(v.x, fmaxf(v.y, v.z));
    h.z = fmaxf(v.y, fmaxf(v.z, v.w));
    h.w = fmaxf(v.z, fmaxf(v.w, r));
    return h;
}

__device__ __forceinline__ float4 max3v(float4 a, float4 b, float4 c) {
    float4 m;
    m.x = fmaxf(a.x, fmaxf(b.x, c.x));
    m.y = fmaxf(a.y, fmaxf(b.y, c.y));
    m.z = fmaxf(a.z, fmaxf(b.z, c.z));
    m.w = fmaxf(a.w, fmaxf(b.w, c.w));
    return m;
}

// F fused steps; 512 threads; each thread owns a 4-row x 4-px quad of a
// 128x64 tile. 2 smem buffers, 1 barrier/step (cur read only pre-barrier;
// dilate and the next erode both read oth). ek carried in registers
// (r1..r4 of the quad dilate = e_{st+1} centers). 64-reg budget.
template<int F, bool FIRST, bool LAST>
__global__ __launch_bounds__(512, 2)
void fused_kernel(int src_sel, int dst_sel) {
    constexpr int R  = F + 1;
    constexpr int H2 = TYO + 2 * R;
    constexpr int BUF = H2 * W2;

    extern __shared__ float smem[];
    float* sX = smem;
    float* sY = smem + BUF;
    __shared__ float sred[32];

    const float* in = (src_sel == 0) ? g_img0 : ((src_sel == 1) ? g_bufA : g_bufB);
    float* eout = (dst_sel == 1) ? g_bufA : g_bufB;

    const int bx = blockIdx.x * TXO;
    const int by = blockIdx.y * TYO;
    const int z  = blockIdx.z;
    const float* img = in + z * NPIX;
    const int tx = threadIdx.x;        // 0..31 (x vector)
    const int ty = threadIdx.y;        // 0..15 (row quad)
    const int tid = ty * 32 + tx;
    const bool border = (blockIdx.x == 0) | (blockIdx.x == gridDim.x - 1) |
                        (blockIdx.y == 0) | (blockIdx.y == gridDim.y - 1);

    // ---- load e_0 tile with halo into sX ----
    if (!border) {
        for (int i = tid; i < 36 * H2; i += 512) {
            int vy = i / 36, vx = i - vy * 36;
            *(float4*)&sX[vy * W2 + 4 * vx] =
                *(const float4*)&img[(by - R + vy) * W + (bx - PADX + 4 * vx)];
        }
    } else {
        for (int i = tid; i < 36 * H2; i += 512) {
            int vy = i / 36, vx = i - vy * 36;
            int gx0 = bx - PADX + 4 * vx;
            int gy  = by - R + vy;
            float4 v = make_float4(INFINITY, INFINITY, INFINITY, INFINITY);
            if ((unsigned)gx0 < W && (unsigned)gy < H)
                v = *(const float4*)&img[gy * W + gx0];
            *(float4*)&sX[vy * W2 + 4 * vx] = v;
        }
    }

    const int py0 = 4 * ty;
    const int gi0 = z * NPIX + (by + py0) * W + (bx + 4 * tx);
    const int oc = (R + py0) * W2 + PADX + 4 * tx;
    const int gx0c = bx + 4 * tx;
    const int gy0c = by + py0;

    float4 sk0, sk1, sk2, sk3;
    if (FIRST) {
        sk0 = make_float4(0.f, 0.f, 0.f, 0.f);
        sk1 = sk0; sk2 = sk0; sk3 = sk0;
    } else {
        sk0 = *(const float4*)&g_skel[gi0];
        sk1 = *(const float4*)&g_skel[gi0 + W];
        sk2 = *(const float4*)&g_skel[gi0 + 2 * W];
        sk3 = *(const float4*)&g_skel[gi0 + 3 * W];
    }
    __syncthreads();

    // ek = e_0 at own center rows (sX stable until the st=1 erode, which is
    // behind the st=0 barrier).
    float4 ek0 = *(float4*)&sX[oc];
    float4 ek1 = *(float4*)&sX[oc + W2];
    float4 ek2 = *(float4*)&sX[oc + 2 * W2];
    float4 ek3 = *(float4*)&sX[oc + 3 * W2];

    float* cur = sX;
    float* oth = sY;

    #pragma unroll
    for (int st = 0; st < F; st++) {
        // ---- erode cur -> oth; rows [1+st, H2-1-st) in pairs; vecs 1..34 ----
        const int npairs = (H2 - 2 - 2 * st) >> 1;
        const int ntask = npairs * 34;
        for (int i = tid; i < ntask; i += 512) {
            int pj = i / 34;
            int vx = i - pj * 34 + 1;
            int y0 = 1 + st + 2 * pj;
            int o1 = y0 * W2 + 4 * vx;
            int o2 = o1 + W2;
            float4 c0 = *(float4*)&cur[o1 - W2];
            float4 c1 = *(float4*)&cur[o1];
            float4 c2 = *(float4*)&cur[o2];
            float4 c3 = *(float4*)&cur[o2 + W2];
            float l1 = cur[o1 - 1], r1 = cur[o1 + 4];
            float l2 = cur[o2 - 1], r2 = cur[o2 + 4];
            float4 e1 = erode5(c0, c1, c2, l1, r1);
            float4 e2 = erode5(c1, c2, c3, l2, r2);
            if (border) {
                int gx0 = bx - PADX + 4 * vx;
                int gy  = by - R + y0;
                bool okx = (unsigned)gx0 < W;
                if (!(okx && (unsigned)gy < H))
                    e1 = make_float4(INFINITY, INFINITY, INFINITY, INFINITY);
                if (!(okx && (unsigned)(gy + 1) < H))
                    e2 = make_float4(INFINITY, INFINITY, INFINITY, INFINITY);
            }
            *(float4*)&oth[o1] = e1;
            *(float4*)&oth[o2] = e2;
        }
        __syncthreads();

        // ---- quad dilate of e_{st+1} (oth), streaming rows to cap liveness ----
        {
            const bool mt = border && (gy0c == 0);          // top image row
            const bool mb = border && (gy0c + 3 == H - 1);  // bottom image row
            const bool ml = border && (gx0c == 0);
            const bool mr = border && (gx0c == W - 4);
            const float NI = -INFINITY;

            // row -1
            float4 r0 = *(float4*)&oth[oc - W2];
            float l0 = oth[oc - W2 - 1], q0 = oth[oc - W2 + 4];
            if (mt) { r0 = make_float4(NI, NI, NI, NI); l0 = NI; q0 = NI; }
            if (ml) l0 = NI;
            if (mr) q0 = NI;
            float4 h0 = hmax3(l0, r0, q0);
            // row 0
            float4 r1 = *(float4*)&oth[oc];
            float l1 = oth[oc - 1], q1 = oth[oc + 4];
            float4 h1;
            { float a = ml ? NI : l1, b = mr ? NI : q1; h1 = hmax3(a, r1, b); }
            // row 1
            float4 r2 = *(float4*)&oth[oc + W2];
            float l2 = oth[oc + W2 - 1], q2 = oth[oc + W2 + 4];
            float4 h2;
            { float a = ml ? NI : l2, b = mr ? NI : q2; h2 = hmax3(a, r2, b); }

            float4 d0 = max3v(h0, h1, h2);
            float4 de0;
            de0.x = fmaxf(ek0.x - d0.x, 0.f);
            de0.y = fmaxf(ek0.y - d0.y, 0.f);
            de0.z = fmaxf(ek0.z - d0.z, 0.f);
            de0.w = fmaxf(ek0.w - d0.w, 0.f);
            if (FIRST && st == 0) sk0 = de0;
            else {
                sk0.x += fmaxf(de0.x - sk0.x * de0.x, 0.f);
                sk0.y += fmaxf(de0.y - sk0.y * de0.y, 0.f);
                sk0.z += fmaxf(de0.z - sk0.z * de0.z, 0.f);
                sk0.w += fmaxf(de0.w - sk0.w * de0.w, 0.f);
            }
            ek0 = r1;   // e_{st+1} row 0 (raw, unmasked)

            // row 2
            float4 r3 = *(float4*)&oth[oc + 2 * W2];
            float l3 = oth[oc + 2 * W2 - 1], q3 = oth[oc + 2 * W2 + 4];
            float4 h3;
            { float a = ml ? NI : l3, b = mr ? NI : q3; h3 = hmax3(a, r3, b); }

            float4 d1 = max3v(h1, h2, h3);
            float4 de1;
            de1.x = fmaxf(ek1.x - d1.x, 0.f);
            de1.y = fmaxf(ek1.y - d1.y, 0.f);
            de1.z = fmaxf(ek1.z - d1.z, 0.f);
            de1.w = fmaxf(ek1.w - d1.w, 0.f);
            if (FIRST && st == 0) sk1 = de1;
            else {
                sk1.x += fmaxf(de1.x - sk1.x * de1.x, 0.f);
                sk1.y += fmaxf(de1.y - sk1.y * de1.y, 0.f);
                sk1.z += fmaxf(de1.z - sk1.z * de1.z, 0.f);
                sk1.w += fmaxf(de1.w - sk1.w * de1.w, 0.f);
            }
            ek1 = r2;

            // row 3
            float4 r4 = *(float4*)&oth[oc + 3 * W2];
            float l4 = oth[oc + 3 * W2 - 1], q4 = oth[oc + 3 * W2 + 4];
            float4 h4;
            { float a = ml ? NI : l4, b = mr ? NI : q4; h4 = hmax3(a, r4, b); }

            float4 d2 = max3v(h2, h3, h4);
            float4 de2;
            de2.x = fmaxf(ek2.x - d2.x, 0.f);
            de2.y = fmaxf(ek2.y - d2.y, 0.f);
            de2.z = fmaxf(ek2.z - d2.z, 0.f);
            de2.w = fmaxf(ek2.w - d2.w, 0.f);
            if (FIRST && st == 0) sk2 = de2;
            else {
                sk2.x += fmaxf(de2.x - sk2.x * de2.x, 0.f);
                sk2.y += fmaxf(de2.y - sk2.y * de2.y, 0.f);
                sk2.z += fmaxf(de2.z - sk2.z * de2.z, 0.f);
                sk2.w += fmaxf(de2.w - sk2.w * de2.w, 0.f);
            }
            ek2 = r3;

            // row 4
            float4 r5 = *(float4*)&oth[oc + 4 * W2];
            float l5 = oth[oc + 4 * W2 - 1], q5 = oth[oc + 4 * W2 + 4];
            if (mb) { r5 = make_float4(NI, NI, NI, NI); l5 = NI; q5 = NI; }
            if (ml) l5 = NI;
            if (mr) q5 = NI;
            float4 h5 = hmax3(l5, r5, q5);

            float4 d3 = max3v(h3, h4, h5);
            float4 de3;
            de3.x = fmaxf(ek3.x - d3.x, 0.f);
            de3.y = fmaxf(ek3.y - d3.y, 0.f);
            de3.z = fmaxf(ek3.z - d3.z, 0.f);
            de3.w = fmaxf(ek3.w - d3.w, 0.f);
            if (FIRST && st == 0) sk3 = de3;
            else {
                sk3.x += fmaxf(de3.x - sk3.x * de3.x, 0.f);
                sk3.y += fmaxf(de3.y - sk3.y * de3.y, 0.f);
                sk3.z += fmaxf(de3.z - sk3.z * de3.z, 0.f);
                sk3.w += fmaxf(de3.w - sk3.w * de3.w, 0.f);
            }
            ek3 = r4;

            if (st == F - 1 && !LAST) {
                *(float4*)&eout[gi0]         = ek0;
                *(float4*)&eout[gi0 + W]     = ek1;
                *(float4*)&eout[gi0 + 2 * W] = ek2;
                *(float4*)&eout[gi0 + 3 * W] = ek3;
                *(float4*)&g_skel[gi0]         = sk0;
                *(float4*)&g_skel[gi0 + W]     = sk1;
                *(float4*)&g_skel[gi0 + 2 * W] = sk2;
                *(float4*)&g_skel[gi0 + 3 * W] = sk3;
            }
        }
        // swap: next erode writes old cur (whose last readers were this
        // step's pre-barrier erode); dilate and next erode both only READ oth.
        float* t0 = cur; cur = oth; oth = t0;
    }

    if (LAST) {
        const int co = (z < 8) ? HALF : -HALF;
        float4 cp0 = *(const float4*)&g_img0[gi0 + co];
        float4 cp1 = *(const float4*)&g_img0[gi0 + W + co];
        float4 cp2 = *(const float4*)&g_img0[gi0 + 2 * W + co];
        float4 cp3 = *(const float4*)&g_img0[gi0 + 3 * W + co];
        float sprod = sk0.x * cp0.x + sk0.y * cp0.y + sk0.z * cp0.z + sk0.w * cp0.w
                    + sk1.x * cp1.x + sk1.y * cp1.y + sk1.z * cp1.z + sk1.w * cp1.w
                    + sk2.x * cp2.x + sk2.y * cp2.y + sk2.z * cp2.z + sk2.w * cp2.w
                    + sk3.x * cp3.x + sk3.y * cp3.y + sk3.z * cp3.z + sk3.w * cp3.w;
        float ssum  = sk0.x + sk0.y + sk0.z + sk0.w
                    + sk1.x + sk1.y + sk1.z + sk1.w
                    + sk2.x + sk2.y + sk2.z + sk2.w
                    + sk3.x + sk3.y + sk3.z + sk3.w;
        #pragma unroll
        for (int o = 16; o; o >>= 1) {
            sprod += __shfl_down_sync(0xffffffffu, sprod, o);
            ssum  += __shfl_down_sync(0xffffffffu, ssum,  o);
        }
        int w = tid >> 5, l = tid & 31;
        if (l == 0) { sred[w] = sprod; sred[16 + w] = ssum; }
        __syncthreads();
        if (tid < 32) {
            float v = sred[tid];
            v += __shfl_down_sync(0xffffffffu, v, 8, 16);
            v += __shfl_down_sync(0xffffffffu, v, 4, 16);
            v += __shfl_down_sync(0xffffffffu, v, 2, 16);
            v += __shfl_down_sync(0xffffffffu, v, 1, 16);
            if (tid == 0) {
                if (z < 8) atomicAdd(&g_acc[0], v); else atomicAdd(&g_acc[2], v);
            }
            if (tid == 16) {
                if (z < 8) atomicAdd(&g_acc[1], v); else atomicAdd(&g_acc[3], v);
            }
        }
    }
}

__global__ void finalize_kernel(float* out) {
    const float SMOOTH = 1.0f;
    float tprec = (g_acc[0] + SMOOTH) / (g_acc[1] + SMOOTH);
    float tsens = (g_acc[2] + SMOOTH) / (g_acc[3] + SMOOTH);
    float cl_dice = 2.0f * tprec * tsens / (tprec + tsens + 1e-7f);
    float dice = (2.0f * g_acc[4] + SMOOTH) / (g_acc[5] + g_acc[6] + SMOOTH);
    float combined = 0.5f * dice + 0.5f * cl_dice;
    out[0] = 1.0f - combined;
}

extern "C" void kernel_launch(void* const* d_in, const int* in_sizes, int n_in,
                              void* d_out, int out_size) {
    const float4* pred = (const float4*)d_in[0];
    const int4* target = (const int4*)d_in[1];

    constexpr int SMEM_F4 = 2 * (TYO + 10) * W2 * 4;   // 2*74*144*4 = 85248
    constexpr int SMEM_F3 = 2 * (TYO + 8)  * W2 * 4;   // 2*72*144*4 = 82944
    static bool attr_done = false;
    if (!attr_done) {
        cudaFuncSetAttribute(fused_kernel<4, true,  false>,
                             cudaFuncAttributeMaxDynamicSharedMemorySize, SMEM_F4);
        cudaFuncSetAttribute(fused_kernel<4, false, false>,
                             cudaFuncAttributeMaxDynamicSharedMemorySize, SMEM_F4);
        cudaFuncSetAttribute(fused_kernel<3, false, true>,
                             cudaFuncAttributeMaxDynamicSharedMemorySize, SMEM_F3);
        attr_done = true;
    }

    zero_acc_kernel<<<1, 32>>>();
    init_kernel<<<2048, 256>>>(pred, target);

    dim3 blk(32, 16);
    dim3 grd(W / TXO, H / TYO, NSL);
    fused_kernel<4, true,  false><<<grd, blk, SMEM_F4>>>(0, 1);  // steps 0-3
    fused_kernel<4, false, false><<<grd, blk, SMEM_F4>>>(1, 2);  // steps 4-7
    fused_kernel<3, false, true ><<<grd, blk, SMEM_F3>>>(2, 2);  // steps 8-10

    finalize_kernel<<<1, 1>>>((float*)d_out);
}